// round 8
// baseline (speedup 1.0000x reference)
#include <cuda_runtime.h>
#include <cuda_fp16.h>

// Fixed problem shapes
constexpr int NN    = 50000;   // nodes
constexpr int F_IN  = 64;
constexpr int HEADS = 4;
constexpr int HID   = 32;
constexpr int C1    = HEADS * HID;  // 128
constexpr int C2    = HID;          // 32
constexpr int CLS   = 3;
constexpr int SLOTS = 96;           // bucket capacity per node (deg ~ Poisson(17))
constexpr int PB    = 64;           // partial accumulator buckets

// ---------------- scratch (device globals) ----------------------------------
__device__ __align__(16) __half g_h1h[NN * C1];   // fp16 layer-1 features
__device__ __align__(16) float g_asrc1[NN * HEADS];
__device__ __align__(16) float g_adst1[NN * HEADS];
__device__ __align__(16) float g_out1[NN * C1];
__device__ __align__(16) __half g_h2h[NN * C2];   // fp16 layer-2 features
__device__ float g_asrc2[NN];
__device__ float g_adst2[NN];
__device__ float g_paccum[PB * C2];               // partial global sums
__device__ int   g_ei64;

// bucket CSR
__device__ int g_cursor[NN];                      // becomes degree after scatter
__device__ int g_sortbuf[NN * SLOTS];

// ---------------- init: self-loop preplacement + dtype detect ----------------
__global__ void k_init(const int* __restrict__ ei, int n) {
    int i = blockIdx.x * blockDim.x + threadIdx.x;
    int stride = gridDim.x * blockDim.x;
    for (; i < n; i += stride) {
        g_cursor[i] = 1;                 // slot 0 = self-loop
        g_sortbuf[i * SLOTS] = i;
        if (i < PB * C2) g_paccum[i] = 0.f;
    }
    if (blockIdx.x == 0 && threadIdx.x == 0) {
        int all_zero = 1;
        for (int j = 1; j < 512; j += 2)
            if (ei[j] != 0) { all_zero = 0; break; }
        g_ei64 = all_zero;
    }
}

__device__ __forceinline__ void load_edge(const int* ei, int idx, int E,
                                          int& src, int& dst) {
    if (g_ei64) {
        const long long* e64 = (const long long*)ei;
        src = (int)e64[idx];
        dst = (int)e64[E + idx];
    } else {
        src = ei[idx];
        dst = ei[E + idx];
    }
}

// ---------------- scatter into buckets (4 edges/thread for atomic ILP) ------
__global__ void k_scatter(const int* __restrict__ ei, int E) {
    int base = (blockIdx.x * blockDim.x + threadIdx.x) * 4;
    int srcs[4], dsts[4];
    #pragma unroll
    for (int u = 0; u < 4; u++) {
        int i = base + u;
        if (i < E) load_edge(ei, i, E, srcs[u], dsts[u]);
        else       dsts[u] = -1;
    }
    int pos[4];
    #pragma unroll
    for (int u = 0; u < 4; u++)
        if (dsts[u] >= 0) pos[u] = atomicAdd(&g_cursor[dsts[u]], 1);
    #pragma unroll
    for (int u = 0; u < 4; u++)
        if (dsts[u] >= 0) g_sortbuf[dsts[u] * SLOTS + pos[u]] = srcs[u];
}

// ---------------- K1: h1 = x @ W1 ; attn coeffs (W in registers) ------------
__global__ void __launch_bounds__(128) k_gemm1(
        const float* __restrict__ x, const float* __restrict__ W1,
        const float* __restrict__ attS, const float* __restrict__ attD, int n) {
    int t = threadIdx.x;   // output column 0..127
    float w[F_IN];
    #pragma unroll
    for (int k = 0; k < F_IN; k++) w[k] = W1[k * C1 + t];

    __shared__ float4 xsh[64 * 16];
    int n0 = blockIdx.x * 64;
    const float4* x4 = (const float4*)x;
    for (int i = t; i < 64 * 16; i += 128) {
        int node = n0 + (i >> 4);
        xsh[i] = (node < n) ? x4[node * 16 + (i & 15)] : make_float4(0.f, 0.f, 0.f, 0.f);
    }
    __syncthreads();

    float aS = attS[t], aD = attD[t];
    int lane = t & 31, wi = t >> 5;
    int nmax = min(64, n - n0);
    for (int nn = 0; nn < nmax; nn++) {
        float a0 = 0.f, a1 = 0.f, a2 = 0.f, a3 = 0.f;
        #pragma unroll
        for (int k4 = 0; k4 < 16; k4++) {
            float4 xv = xsh[nn * 16 + k4];
            a0 += xv.x * w[k4 * 4 + 0];
            a1 += xv.y * w[k4 * 4 + 1];
            a2 += xv.z * w[k4 * 4 + 2];
            a3 += xv.w * w[k4 * 4 + 3];
        }
        float acc = (a0 + a1) + (a2 + a3);
        g_h1h[(n0 + nn) * C1 + t] = __float2half(acc);
        float vs = acc * aS, vd = acc * aD;
        #pragma unroll
        for (int o = 16; o > 0; o >>= 1) {
            vs += __shfl_down_sync(0xffffffffu, vs, o);
            vd += __shfl_down_sync(0xffffffffu, vd, o);
        }
        if (lane == 0) {
            g_asrc1[(n0 + nn) * HEADS + wi] = vs;
            g_adst1[(n0 + nn) * HEADS + wi] = vd;
        }
    }
}

// ---------------- K2: edge pass 1, bucket CSR, warp per destination ---------
// Warp-uniform chunk-4 loop: no predicated waste; half2 FMA accumulation.
__global__ void k_edge1(int n) {
    int gw = (blockIdx.x * blockDim.x + threadIdx.x) >> 5;
    if (gw >= n) return;
    int lane = threadIdx.x & 31;
    int h = lane >> 3;
    float aD = g_adst1[gw * HEADS + h];
    int start = gw * SLOTS, deg = g_cursor[gw];

    const uint2* h1v = reinterpret_cast<const uint2*>(g_h1h);
    __half2 acc01 = __float2half2_rn(0.f);
    __half2 acc23 = __float2half2_rn(0.f);
    float psum = 0.f;

    for (int i = 0; i < deg; i += 32) {
        int myj = i + lane;
        int s = (myj < deg) ? g_sortbuf[start + myj] : 0;
        int lim = min(32, deg - i);
        int j = 0;
        for (; j + 4 <= lim; j += 4) {
            int s0 = __shfl_sync(0xffffffffu, s, j);
            int s1 = __shfl_sync(0xffffffffu, s, j + 1);
            int s2 = __shfl_sync(0xffffffffu, s, j + 2);
            int s3 = __shfl_sync(0xffffffffu, s, j + 3);
            float e0 = g_asrc1[s0 * HEADS + h] + aD;
            float e1 = g_asrc1[s1 * HEADS + h] + aD;
            float e2 = g_asrc1[s2 * HEADS + h] + aD;
            float e3 = g_asrc1[s3 * HEADS + h] + aD;
            uint2 r0 = h1v[s0 * 32 + lane];
            uint2 r1 = h1v[s1 * 32 + lane];
            uint2 r2 = h1v[s2 * 32 + lane];
            uint2 r3 = h1v[s3 * 32 + lane];
            e0 = fmaxf(e0, 0.2f * e0); e1 = fmaxf(e1, 0.2f * e1);
            e2 = fmaxf(e2, 0.2f * e2); e3 = fmaxf(e3, 0.2f * e3);
            float p0 = __expf(e0), p1 = __expf(e1);
            float p2 = __expf(e2), p3 = __expf(e3);
            __half2 ph0 = __float2half2_rn(p0), ph1 = __float2half2_rn(p1);
            __half2 ph2 = __float2half2_rn(p2), ph3 = __float2half2_rn(p3);
            acc01 = __hfma2(ph0, *reinterpret_cast<__half2*>(&r0.x), acc01);
            acc23 = __hfma2(ph0, *reinterpret_cast<__half2*>(&r0.y), acc23);
            acc01 = __hfma2(ph1, *reinterpret_cast<__half2*>(&r1.x), acc01);
            acc23 = __hfma2(ph1, *reinterpret_cast<__half2*>(&r1.y), acc23);
            acc01 = __hfma2(ph2, *reinterpret_cast<__half2*>(&r2.x), acc01);
            acc23 = __hfma2(ph2, *reinterpret_cast<__half2*>(&r2.y), acc23);
            acc01 = __hfma2(ph3, *reinterpret_cast<__half2*>(&r3.x), acc01);
            acc23 = __hfma2(ph3, *reinterpret_cast<__half2*>(&r3.y), acc23);
            psum += (p0 + p1) + (p2 + p3);
        }
        for (; j < lim; j++) {
            int s0 = __shfl_sync(0xffffffffu, s, j);
            float e0 = g_asrc1[s0 * HEADS + h] + aD;
            e0 = fmaxf(e0, 0.2f * e0);
            float p0 = __expf(e0);
            uint2 r0 = h1v[s0 * 32 + lane];
            __half2 ph0 = __float2half2_rn(p0);
            acc01 = __hfma2(ph0, *reinterpret_cast<__half2*>(&r0.x), acc01);
            acc23 = __hfma2(ph0, *reinterpret_cast<__half2*>(&r0.y), acc23);
            psum += p0;
        }
    }
    float inv = 1.0f / psum;
    float2 f01 = __half22float2(acc01);
    float2 f23 = __half22float2(acc23);
    float4 o;
    o.x = f01.x * inv; o.y = f01.y * inv;
    o.z = f23.x * inv; o.w = f23.y * inv;
    reinterpret_cast<float4*>(g_out1)[gw * 32 + lane] = o;
}

// ---------------- K3: bias+ELU, GEMM2 (W2 k-chunks in regs), attn coeffs ----
__global__ void __launch_bounds__(256) k_node1(
        const float* __restrict__ W2, const float* __restrict__ b1,
        const float* __restrict__ attS2, const float* __restrict__ attD2, int n) {
    int tx = threadIdx.x;        // col 0..31
    int ty = threadIdx.y;        // k-chunk 0..7
    int t = ty * 32 + tx;

    float w2r[16];
    #pragma unroll
    for (int k = 0; k < 16; k++) w2r[k] = W2[(ty * 16 + k) * C2 + tx];

    __shared__ float hsh[16 * C1];
    __shared__ float ps[8][16][32];

    int n0 = blockIdx.x * 16;
    for (int i = t; i < 16 * C1; i += 256) {
        int nn = i >> 7, k = i & 127;
        int node = n0 + nn;
        float v = 0.f;
        if (node < n) {
            v = g_out1[node * C1 + k] + b1[k];
            v = v > 0.f ? v : expm1f(v);
        }
        hsh[i] = v;
    }
    __syncthreads();

    const float4* h4 = (const float4*)hsh;
    for (int nn = 0; nn < 16; nn++) {
        float acc = 0.f;
        #pragma unroll
        for (int k4 = 0; k4 < 4; k4++) {
            float4 hv = h4[nn * 32 + ty * 4 + k4];
            acc += hv.x * w2r[k4 * 4 + 0] + hv.y * w2r[k4 * 4 + 1]
                 + hv.z * w2r[k4 * 4 + 2] + hv.w * w2r[k4 * 4 + 3];
        }
        ps[ty][nn][tx] = acc;
    }
    __syncthreads();

    float aS = attS2[tx], aD = attD2[tx];
    #pragma unroll
    for (int pp = 0; pp < 2; pp++) {
        int nn = pp * 8 + (t >> 5);
        int col = tx;
        float s = 0.f;
        #pragma unroll
        for (int j = 0; j < 8; j++) s += ps[j][nn][col];
        int node = n0 + nn;
        float vs = s * aS, vd = s * aD;
        #pragma unroll
        for (int o = 16; o > 0; o >>= 1) {
            vs += __shfl_down_sync(0xffffffffu, vs, o);
            vd += __shfl_down_sync(0xffffffffu, vd, o);
        }
        if (node < n) {
            g_h2h[node * C2 + col] = __float2half(s);
            if (col == 0) { g_asrc2[node] = vs; g_adst2[node] = vd; }
        }
    }
}

// ---------------- K4: edge pass 2 + fused global-sum -------------------------
__global__ void k_edge2(int n) {
    __shared__ float sblock[C2];
    int t = threadIdx.x;
    if (t < C2) sblock[t] = 0.f;
    __syncthreads();

    int gw = (blockIdx.x * blockDim.x + t) >> 5;
    int lane = t & 31;
    if (gw < n) {
        int g = lane >> 3, l8 = lane & 7;
        float aD = g_adst2[gw];
        int start = gw * SLOTS, deg = g_cursor[gw];

        const uint2* h2v = reinterpret_cast<const uint2*>(g_h2h);
        __half2 acc01 = __float2half2_rn(0.f);
        __half2 acc23 = __float2half2_rn(0.f);
        float psum = 0.f;
        #pragma unroll 4
        for (int i = g; i < deg; i += 4) {
            int src = g_sortbuf[start + i];
            float e = g_asrc2[src] + aD;
            e = fmaxf(e, 0.2f * e);
            float p = __expf(e);
            uint2 raw = h2v[src * 8 + l8];
            __half2 ph = __float2half2_rn(p);
            acc01 = __hfma2(ph, *reinterpret_cast<__half2*>(&raw.x), acc01);
            acc23 = __hfma2(ph, *reinterpret_cast<__half2*>(&raw.y), acc23);
            psum += p;
        }
        float2 f01 = __half22float2(acc01);
        float2 f23 = __half22float2(acc23);
        float ax = f01.x, ay = f01.y, az = f23.x, aw = f23.y;
        #pragma unroll
        for (int o = 8; o <= 16; o <<= 1) {
            ax += __shfl_xor_sync(0xffffffffu, ax, o);
            ay += __shfl_xor_sync(0xffffffffu, ay, o);
            az += __shfl_xor_sync(0xffffffffu, az, o);
            aw += __shfl_xor_sync(0xffffffffu, aw, o);
            psum += __shfl_xor_sync(0xffffffffu, psum, o);
        }
        if (lane < 8) {
            float inv = 1.0f / psum;
            int c = lane * 4;
            atomicAdd(&sblock[c + 0], ax * inv);
            atomicAdd(&sblock[c + 1], ay * inv);
            atomicAdd(&sblock[c + 2], az * inv);
            atomicAdd(&sblock[c + 3], aw * inv);
        }
    }
    __syncthreads();
    if (t < C2)
        atomicAdd(&g_paccum[(blockIdx.x & (PB - 1)) * C2 + t], sblock[t]);
}

// ---------------- K5: reduce partials -> mean -> logits -> softmax -----------
__global__ void k_out(const float* __restrict__ b2,
                      const float* __restrict__ linW, const float* __restrict__ linb,
                      float* __restrict__ out, int n) {
    __shared__ float tot[C2];
    int t = threadIdx.x;   // 32 threads
    float s = 0.f;
    for (int b = 0; b < PB; b++) s += g_paccum[b * C2 + t];
    tot[t] = s / (float)n + b2[t];
    __syncwarp();
    if (t == 0) {
        float logits[CLS];
        for (int j = 0; j < CLS; j++) {
            float acc = linb[j];
            for (int c = 0; c < C2; c++)
                acc += tot[c] * linW[c * CLS + j];
            logits[j] = acc;
        }
        float m = fmaxf(logits[0], fmaxf(logits[1], logits[2]));
        float e0 = expf(logits[0] - m);
        float e1 = expf(logits[1] - m);
        float e2 = expf(logits[2] - m);
        float sm = e0 + e1 + e2;
        out[0] = e0 / sm; out[1] = e1 / sm; out[2] = e2 / sm;
    }
}

// ---------------- launcher ---------------------------------------------------
extern "C" void kernel_launch(void* const* d_in, const int* in_sizes, int n_in,
                              void* d_out, int out_size) {
    const float* x        = (const float*)d_in[0];
    const float* W1       = (const float*)d_in[1];
    const float* att_src1 = (const float*)d_in[2];
    const float* att_dst1 = (const float*)d_in[3];
    const float* b1       = (const float*)d_in[4];
    const float* W2       = (const float*)d_in[5];
    const float* att_src2 = (const float*)d_in[6];
    const float* att_dst2 = (const float*)d_in[7];
    const float* b2       = (const float*)d_in[8];
    const float* linW     = (const float*)d_in[9];
    const float* linb     = (const float*)d_in[10];
    const int*   ei       = (const int*)d_in[11];

    int n  = in_sizes[0] / F_IN;       // 50000
    int E  = in_sizes[11] / 2;         // 800000
    float* out = (float*)d_out;

    // One-time host-side stream/event creation (no device allocation).
    static cudaStream_t sB = nullptr;
    static cudaEvent_t evFork = nullptr, evJoin = nullptr;
    if (sB == nullptr) {
        cudaStreamCreateWithFlags(&sB, cudaStreamNonBlocking);
        cudaEventCreateWithFlags(&evFork, cudaEventDisableTiming);
        cudaEventCreateWithFlags(&evJoin, cudaEventDisableTiming);
    }

    // Fork: gemm1 (depends only on x/W1) runs concurrent with init+scatter.
    cudaEventRecord(evFork, 0);
    cudaStreamWaitEvent(sB, evFork, 0);
    k_gemm1<<<(n + 63) / 64, 128, 0, sB>>>(x, W1, att_src1, att_dst1, n);
    cudaEventRecord(evJoin, sB);

    k_init<<<64, 256>>>(ei, n);
    k_scatter<<<(E + 1023) / 1024, 256>>>(ei, E);

    // Join before edge1 (needs both gemm1 outputs and CSR).
    cudaStreamWaitEvent(0, evJoin, 0);

    {
        long long threads = (long long)n * 32;
        k_edge1<<<(int)((threads + 255) / 256), 256>>>(n);
    }

    k_node1<<<(n + 15) / 16, dim3(32, 8)>>>(W2, b1, att_src2, att_dst2, n);

    {
        long long threads = (long long)n * 32;
        k_edge2<<<(int)((threads + 255) / 256), 256>>>(n);
    }

    k_out<<<1, 32>>>(b2, linW, linb, out, n);
}

// round 9
// speedup vs baseline: 1.3633x; 1.3633x over previous
#include <cuda_runtime.h>
#include <cuda_fp16.h>

// Fixed problem shapes
constexpr int NN    = 50000;   // nodes
constexpr int F_IN  = 64;
constexpr int HEADS = 4;
constexpr int HID   = 32;
constexpr int C1    = HEADS * HID;  // 128
constexpr int C2    = HID;          // 32
constexpr int CLS   = 3;
constexpr int SLOTS = 96;           // bucket capacity per node (deg ~ Poisson(17))
constexpr int PB    = 64;           // partial accumulator buckets

// ---------------- scratch (device globals) ----------------------------------
__device__ __align__(16) __half g_h1h[NN * C1];   // fp16 layer-1 features
__device__ __align__(16) float g_asrc1[NN * HEADS];
__device__ __align__(16) float g_adst1[NN * HEADS];
__device__ __align__(16) float g_out1[NN * C1];
__device__ __align__(16) __half g_h2h[NN * C2];   // fp16 layer-2 features
__device__ float g_asrc2[NN];
__device__ float g_adst2[NN];
__device__ float g_paccum[PB * C2];               // partial global sums
__device__ int   g_ei64;

// bucket CSR
__device__ int g_cursor[NN];                      // becomes degree after scatter
__device__ int g_sortbuf[NN * SLOTS];

// ---------------- init: self-loop preplacement + dtype detect ----------------
__global__ void k_init(const int* __restrict__ ei, int n) {
    int i = blockIdx.x * blockDim.x + threadIdx.x;
    int stride = gridDim.x * blockDim.x;
    for (; i < n; i += stride) {
        g_cursor[i] = 1;                 // slot 0 = self-loop
        g_sortbuf[i * SLOTS] = i;
        if (i < PB * C2) g_paccum[i] = 0.f;
    }
    if (blockIdx.x == 0 && threadIdx.x == 0) {
        int all_zero = 1;
        for (int j = 1; j < 512; j += 2)
            if (ei[j] != 0) { all_zero = 0; break; }
        g_ei64 = all_zero;
    }
}

__device__ __forceinline__ void load_edge(const int* ei, int idx, int E,
                                          int& src, int& dst) {
    if (g_ei64) {
        const long long* e64 = (const long long*)ei;
        src = (int)e64[idx];
        dst = (int)e64[E + idx];
    } else {
        src = ei[idx];
        dst = ei[E + idx];
    }
}

// ---------------- scatter into buckets (4 edges/thread for atomic ILP) ------
__global__ void k_scatter(const int* __restrict__ ei, int E) {
    int base = (blockIdx.x * blockDim.x + threadIdx.x) * 4;
    int srcs[4], dsts[4];
    #pragma unroll
    for (int u = 0; u < 4; u++) {
        int i = base + u;
        if (i < E) load_edge(ei, i, E, srcs[u], dsts[u]);
        else       dsts[u] = -1;
    }
    int pos[4];
    #pragma unroll
    for (int u = 0; u < 4; u++)
        if (dsts[u] >= 0) pos[u] = atomicAdd(&g_cursor[dsts[u]], 1);
    #pragma unroll
    for (int u = 0; u < 4; u++)
        if (dsts[u] >= 0) g_sortbuf[dsts[u] * SLOTS + pos[u]] = srcs[u];
}

// ---------------- K1: h1 = x @ W1 ; attn coeffs (W in registers) ------------
__global__ void __launch_bounds__(128) k_gemm1(
        const float* __restrict__ x, const float* __restrict__ W1,
        const float* __restrict__ attS, const float* __restrict__ attD, int n) {
    int t = threadIdx.x;   // output column 0..127
    float w[F_IN];
    #pragma unroll
    for (int k = 0; k < F_IN; k++) w[k] = W1[k * C1 + t];

    __shared__ float4 xsh[64 * 16];
    int n0 = blockIdx.x * 64;
    const float4* x4 = (const float4*)x;
    for (int i = t; i < 64 * 16; i += 128) {
        int node = n0 + (i >> 4);
        xsh[i] = (node < n) ? x4[node * 16 + (i & 15)] : make_float4(0.f, 0.f, 0.f, 0.f);
    }
    __syncthreads();

    float aS = attS[t], aD = attD[t];
    int lane = t & 31, wi = t >> 5;
    int nmax = min(64, n - n0);
    for (int nn = 0; nn < nmax; nn++) {
        float a0 = 0.f, a1 = 0.f, a2 = 0.f, a3 = 0.f;
        #pragma unroll
        for (int k4 = 0; k4 < 16; k4++) {
            float4 xv = xsh[nn * 16 + k4];
            a0 += xv.x * w[k4 * 4 + 0];
            a1 += xv.y * w[k4 * 4 + 1];
            a2 += xv.z * w[k4 * 4 + 2];
            a3 += xv.w * w[k4 * 4 + 3];
        }
        float acc = (a0 + a1) + (a2 + a3);
        g_h1h[(n0 + nn) * C1 + t] = __float2half(acc);
        float vs = acc * aS, vd = acc * aD;
        #pragma unroll
        for (int o = 16; o > 0; o >>= 1) {
            vs += __shfl_down_sync(0xffffffffu, vs, o);
            vd += __shfl_down_sync(0xffffffffu, vd, o);
        }
        if (lane == 0) {
            g_asrc1[(n0 + nn) * HEADS + wi] = vs;
            g_adst1[(n0 + nn) * HEADS + wi] = vd;
        }
    }
}

// ---------------- K2: edge pass 1, bucket CSR, warp per destination ---------
// 32-batch split into 4 warp-uniformly guarded 8-wide predicated sub-blocks:
// statically unrolled body (good SASS), dead sub-blocks skipped by branch.
__global__ void k_edge1(int n) {
    int gw = (blockIdx.x * blockDim.x + threadIdx.x) >> 5;
    if (gw >= n) return;
    int lane = threadIdx.x & 31;
    int h = lane >> 3;
    float aD = g_adst1[gw * HEADS + h];
    int start = gw * SLOTS, deg = g_cursor[gw];

    const uint2* h1v = reinterpret_cast<const uint2*>(g_h1h);
    float4 acc = make_float4(0.f, 0.f, 0.f, 0.f);
    float psum = 0.f;
    for (int i = 0; i < deg; i += 32) {
        int myj = i + lane;
        int s = (myj < deg) ? g_sortbuf[start + myj] : -1;
        #pragma unroll
        for (int b = 0; b < 4; b++) {
            if (i + b * 8 < deg) {               // warp-uniform guard
                #pragma unroll
                for (int j = b * 8; j < b * 8 + 8; j++) {
                    int src = __shfl_sync(0xffffffffu, s, j);
                    if (src >= 0) {
                        float e = g_asrc1[src * HEADS + h] + aD;
                        e = fmaxf(e, 0.2f * e);
                        float p = __expf(e);
                        uint2 raw = h1v[src * 32 + lane];
                        float2 f01 = __half22float2(*reinterpret_cast<__half2*>(&raw.x));
                        float2 f23 = __half22float2(*reinterpret_cast<__half2*>(&raw.y));
                        acc.x += p * f01.x; acc.y += p * f01.y;
                        acc.z += p * f23.x; acc.w += p * f23.y;
                        psum += p;
                    }
                }
            }
        }
    }
    float inv = 1.0f / psum;
    acc.x *= inv; acc.y *= inv; acc.z *= inv; acc.w *= inv;
    reinterpret_cast<float4*>(g_out1)[gw * 32 + lane] = acc;
}

// ---------------- K3: bias+ELU, GEMM2 (W2 k-chunks in regs), attn coeffs ----
__global__ void __launch_bounds__(256) k_node1(
        const float* __restrict__ W2, const float* __restrict__ b1,
        const float* __restrict__ attS2, const float* __restrict__ attD2, int n) {
    int tx = threadIdx.x;        // col 0..31
    int ty = threadIdx.y;        // k-chunk 0..7
    int t = ty * 32 + tx;

    float w2r[16];
    #pragma unroll
    for (int k = 0; k < 16; k++) w2r[k] = W2[(ty * 16 + k) * C2 + tx];

    __shared__ float hsh[16 * C1];
    __shared__ float ps[8][16][32];

    int n0 = blockIdx.x * 16;
    for (int i = t; i < 16 * C1; i += 256) {
        int nn = i >> 7, k = i & 127;
        int node = n0 + nn;
        float v = 0.f;
        if (node < n) {
            v = g_out1[node * C1 + k] + b1[k];
            v = v > 0.f ? v : expm1f(v);
        }
        hsh[i] = v;
    }
    __syncthreads();

    const float4* h4 = (const float4*)hsh;
    for (int nn = 0; nn < 16; nn++) {
        float acc = 0.f;
        #pragma unroll
        for (int k4 = 0; k4 < 4; k4++) {
            float4 hv = h4[nn * 32 + ty * 4 + k4];
            acc += hv.x * w2r[k4 * 4 + 0] + hv.y * w2r[k4 * 4 + 1]
                 + hv.z * w2r[k4 * 4 + 2] + hv.w * w2r[k4 * 4 + 3];
        }
        ps[ty][nn][tx] = acc;
    }
    __syncthreads();

    float aS = attS2[tx], aD = attD2[tx];
    #pragma unroll
    for (int pp = 0; pp < 2; pp++) {
        int nn = pp * 8 + (t >> 5);
        int col = tx;
        float s = 0.f;
        #pragma unroll
        for (int j = 0; j < 8; j++) s += ps[j][nn][col];
        int node = n0 + nn;
        float vs = s * aS, vd = s * aD;
        #pragma unroll
        for (int o = 16; o > 0; o >>= 1) {
            vs += __shfl_down_sync(0xffffffffu, vs, o);
            vd += __shfl_down_sync(0xffffffffu, vd, o);
        }
        if (node < n) {
            g_h2h[node * C2 + col] = __float2half(s);
            if (col == 0) { g_asrc2[node] = vs; g_adst2[node] = vd; }
        }
    }
}

// ---------------- K4: edge pass 2 + fused global-sum -------------------------
__global__ void k_edge2(int n) {
    __shared__ float sblock[C2];
    int t = threadIdx.x;
    if (t < C2) sblock[t] = 0.f;
    __syncthreads();

    int gw = (blockIdx.x * blockDim.x + t) >> 5;
    int lane = t & 31;
    if (gw < n) {
        int g = lane >> 3, l8 = lane & 7;
        float aD = g_adst2[gw];
        int start = gw * SLOTS, deg = g_cursor[gw];

        const uint2* h2v = reinterpret_cast<const uint2*>(g_h2h);
        float4 acc = make_float4(0.f, 0.f, 0.f, 0.f);
        float psum = 0.f;
        #pragma unroll 4
        for (int i = g; i < deg; i += 4) {
            int src = g_sortbuf[start + i];
            float e = g_asrc2[src] + aD;
            e = fmaxf(e, 0.2f * e);
            float p = __expf(e);
            uint2 raw = h2v[src * 8 + l8];
            float2 f01 = __half22float2(*reinterpret_cast<__half2*>(&raw.x));
            float2 f23 = __half22float2(*reinterpret_cast<__half2*>(&raw.y));
            acc.x += p * f01.x; acc.y += p * f01.y;
            acc.z += p * f23.x; acc.w += p * f23.y;
            psum += p;
        }
        #pragma unroll
        for (int o = 8; o <= 16; o <<= 1) {
            acc.x += __shfl_xor_sync(0xffffffffu, acc.x, o);
            acc.y += __shfl_xor_sync(0xffffffffu, acc.y, o);
            acc.z += __shfl_xor_sync(0xffffffffu, acc.z, o);
            acc.w += __shfl_xor_sync(0xffffffffu, acc.w, o);
            psum  += __shfl_xor_sync(0xffffffffu, psum,  o);
        }
        if (lane < 8) {
            float inv = 1.0f / psum;
            int c = lane * 4;
            atomicAdd(&sblock[c + 0], acc.x * inv);
            atomicAdd(&sblock[c + 1], acc.y * inv);
            atomicAdd(&sblock[c + 2], acc.z * inv);
            atomicAdd(&sblock[c + 3], acc.w * inv);
        }
    }
    __syncthreads();
    if (t < C2)
        atomicAdd(&g_paccum[(blockIdx.x & (PB - 1)) * C2 + t], sblock[t]);
}

// ---------------- K5: reduce partials -> mean -> logits -> softmax -----------
__global__ void k_out(const float* __restrict__ b2,
                      const float* __restrict__ linW, const float* __restrict__ linb,
                      float* __restrict__ out, int n) {
    __shared__ float tot[C2];
    int t = threadIdx.x;   // 32 threads
    float s = 0.f;
    for (int b = 0; b < PB; b++) s += g_paccum[b * C2 + t];
    tot[t] = s / (float)n + b2[t];
    __syncwarp();
    if (t == 0) {
        float logits[CLS];
        for (int j = 0; j < CLS; j++) {
            float acc = linb[j];
            for (int c = 0; c < C2; c++)
                acc += tot[c] * linW[c * CLS + j];
            logits[j] = acc;
        }
        float m = fmaxf(logits[0], fmaxf(logits[1], logits[2]));
        float e0 = expf(logits[0] - m);
        float e1 = expf(logits[1] - m);
        float e2 = expf(logits[2] - m);
        float sm = e0 + e1 + e2;
        out[0] = e0 / sm; out[1] = e1 / sm; out[2] = e2 / sm;
    }
}

// ---------------- launcher ---------------------------------------------------
extern "C" void kernel_launch(void* const* d_in, const int* in_sizes, int n_in,
                              void* d_out, int out_size) {
    const float* x        = (const float*)d_in[0];
    const float* W1       = (const float*)d_in[1];
    const float* att_src1 = (const float*)d_in[2];
    const float* att_dst1 = (const float*)d_in[3];
    const float* b1       = (const float*)d_in[4];
    const float* W2       = (const float*)d_in[5];
    const float* att_src2 = (const float*)d_in[6];
    const float* att_dst2 = (const float*)d_in[7];
    const float* b2       = (const float*)d_in[8];
    const float* linW     = (const float*)d_in[9];
    const float* linb     = (const float*)d_in[10];
    const int*   ei       = (const int*)d_in[11];

    int n  = in_sizes[0] / F_IN;       // 50000
    int E  = in_sizes[11] / 2;         // 800000
    float* out = (float*)d_out;

    k_init<<<64, 256>>>(ei, n);
    k_scatter<<<(E + 1023) / 1024, 256>>>(ei, E);

    k_gemm1<<<(n + 63) / 64, 128>>>(x, W1, att_src1, att_dst1, n);

    {
        long long threads = (long long)n * 32;
        k_edge1<<<(int)((threads + 255) / 256), 256>>>(n);
    }

    k_node1<<<(n + 15) / 16, dim3(32, 8)>>>(W2, b1, att_src2, att_dst2, n);

    {
        long long threads = (long long)n * 32;
        k_edge2<<<(int)((threads + 255) / 256), 256>>>(n);
    }

    k_out<<<1, 32>>>(b2, linW, linb, out, n);
}